// round 8
// baseline (speedup 1.0000x reference)
#include <cuda_runtime.h>
#include <math.h>
#include <stdint.h>

#define B_  4
#define T_  2048
#define E_  1024
#define H_  16
#define D_  64
#define CH  128
#define NC  (T_/CH)      // 16
#define M_  (B_*T_)      // 8192
#define EPS 1e-6f

// ---------------- scratch (no allocations allowed) ----------------
__device__ float g_q[M_*E_];
__device__ float g_k[M_*E_];
__device__ float g_v[M_*E_];
__device__ float g_y[M_*E_];
__device__ float g_xc[M_*E_];      // tf32-rounded + k-permuted x (later: y)
__device__ float g_wqc[E_*E_];
__device__ float g_wkc[E_*E_];
__device__ float g_wvc[E_*E_];
__device__ float g_wpc[E_*E_];
__device__ float g_kv[B_*H_*NC*D_*D_];
__device__ float g_zk[B_*H_*NC*D_];
__device__ float g_S [B_*H_*NC*D_*D_];
__device__ float g_Z [B_*H_*NC*D_];

// =================================================================
// helpers
// =================================================================
__device__ __forceinline__ uint32_t smem_u32(const void* p){
    uint32_t a;
    asm("{ .reg .u64 t; cvta.to.shared.u64 t, %1; cvt.u32.u64 %0, t; }" : "=r"(a) : "l"(p));
    return a;
}
__device__ __forceinline__ void cpasync16(uint32_t dst, const void* src){
    asm volatile("cp.async.cg.shared.global [%0], [%1], 16;" :: "r"(dst), "l"(src));
}
__device__ __forceinline__ void cp_commit(){ asm volatile("cp.async.commit_group;" ::: "memory"); }
__device__ __forceinline__ void cp_wait1(){ asm volatile("cp.async.wait_group 1;" ::: "memory"); }

__device__ __forceinline__ float f2tf32f(float v){
    uint32_t u;
    asm("cvt.rna.tf32.f32 %0, %1;" : "=r"(u) : "f"(v));
    return __uint_as_float(u);
}
__device__ __forceinline__ void mma_tf32_16x8x8(float* c, const uint32_t* a, const uint32_t* b){
    asm volatile(
        "mma.sync.aligned.m16n8k8.row.col.f32.tf32.tf32.f32 "
        "{%0,%1,%2,%3}, {%4,%5,%6,%7}, {%8,%9}, {%0,%1,%2,%3};"
        : "+f"(c[0]), "+f"(c[1]), "+f"(c[2]), "+f"(c[3])
        : "r"(a[0]), "r"(a[1]), "r"(a[2]), "r"(a[3]), "r"(b[0]), "r"(b[1]));
}

// =================================================================
// convert: rna tf32 rounding + k-permutation within each 8-group:
// position(j) = (j&3)*2 + (j>>2)   (so pair (cq, cq+4) lands adjacent)
// =================================================================
__global__ __launch_bounds__(256)
void convert_perm(const float* __restrict__ in, float* __restrict__ out, int n){
    int i = blockIdx.x * 256 + threadIdx.x;
    if (i >= n) return;
    int base = i & ~7, j = i & 7;
    int pos = ((j & 3) << 1) | (j >> 2);
    out[base + pos] = f2tf32f(in[i]);
}

// =================================================================
// tf32 mma.sync GEMM core.  Inputs pre-rounded to tf32 + k-permuted.
// tile 128x128, K chunks of 32, 3-stage cp.async, ROWF=40 padding
// (conflict-free LDS.64 fragment loads).
// 8 warps as 4(m) x 2(n); warp tile 32x64 -> 2 m-frags x 8 n-frags.
// =================================================================
#define TM 128
#define TN 128
#define TK 32
#define NS 3
#define NCHUNK (E_/TK)                    // 32
#define ROWF 40                           // padded row stride (floats)
#define TILE_FLOATS (128*ROWF)            // 5120
#define STAGE_FLOATS (2*TILE_FLOATS)      // A then W
#define GEMM_SMEM (NS*STAGE_FLOATS*4)     // 122880 bytes

__device__ __forceinline__ void load_chunk(const float* __restrict__ A,
                                           const float* __restrict__ W,
                                           int m0, int n0, int k0,
                                           uint32_t sA, uint32_t sW, int tid){
#pragma unroll
    for (int it = 0; it < 4; it++){
        int idx = tid + it*256;            // 0..1023
        int row = idx >> 3;                // 0..127
        int kq  = idx & 7;                 // float4 within the 32-float k-chunk
        uint32_t soff = (row*ROWF + kq*4) * 4;
        cpasync16(sA + soff, A + (size_t)(m0+row)*E_ + k0 + kq*4);
        cpasync16(sW + soff, W + (size_t)(n0+row)*E_ + k0 + kq*4);
    }
}

__device__ __forceinline__ void gemm_core(const float* __restrict__ A,
                                          const float* __restrict__ W,
                                          float* sm, int m0, int n0,
                                          float acc[2][8][4]){
    const int tid = threadIdx.x;
    const int wid = tid >> 5, lane = tid & 31;
    const int mw0 = (wid >> 1) * 32;
    const int nw0 = (wid & 1) * 64;
    const int r  = lane >> 2;
    const int cq = lane & 3;
    const uint32_t sb = smem_u32(sm);

#pragma unroll
    for (int c = 0; c < NS-1; c++){
        uint32_t st = sb + c*STAGE_FLOATS*4;
        load_chunk(A, W, m0, n0, c*TK, st, st + TILE_FLOATS*4, tid);
        cp_commit();
    }

    for (int c = 0; c < NCHUNK; c++){
        cp_wait1();
        __syncthreads();
        if (c + 2 < NCHUNK){
            uint32_t st = sb + ((c+2)%NS)*STAGE_FLOATS*4;
            load_chunk(A, W, m0, n0, (c+2)*TK, st, st + TILE_FLOATS*4, tid);
        }
        cp_commit();

        const float* fa = sm + (c%NS)*STAGE_FLOATS;
        const float* fw = fa + TILE_FLOATS;

#pragma unroll
        for (int ks = 0; ks < 4; ks++){
            const int kb = ks*8 + cq*2;
            uint32_t afr[2][4];
#pragma unroll
            for (int mi = 0; mi < 2; mi++){
                const float* ap = fa + (mw0 + mi*16 + r)*ROWF + kb;
                uint2 lo = *(const uint2*)ap;             // a0 (k=cq), a2 (k=cq+4)
                uint2 hi = *(const uint2*)(ap + 8*ROWF);  // a1, a3 (row+8)
                afr[mi][0] = lo.x; afr[mi][1] = hi.x;
                afr[mi][2] = lo.y; afr[mi][3] = hi.y;
            }
#pragma unroll
            for (int ni = 0; ni < 8; ni++){
                const float* bp = fw + (nw0 + ni*8 + r)*ROWF + kb;
                uint2 bb = *(const uint2*)bp;             // b0, b1
                uint32_t bfr[2] = {bb.x, bb.y};
#pragma unroll
                for (int mi = 0; mi < 2; mi++)
                    mma_tf32_16x8x8(acc[mi][ni], afr[mi], bfr);
            }
        }
        __syncthreads();
    }
}

// fused q/k/v projection: blockIdx.x in [0,24): which = x>>3
__global__ __launch_bounds__(256)
void tc_gemm_qkv(const float* __restrict__ A,
                 const float* __restrict__ W0, const float* __restrict__ W1,
                 const float* __restrict__ W2,
                 float* __restrict__ C0, float* __restrict__ C1,
                 float* __restrict__ C2)
{
    extern __shared__ float sm[];
    const int which = blockIdx.x >> 3;
    const int m0 = blockIdx.y * TM, n0 = (blockIdx.x & 7) * TN;
    const float* W = (which == 0) ? W0 : (which == 1) ? W1 : W2;
    float* C       = (which == 0) ? C0 : (which == 1) ? C1 : C2;
    const bool act = (which < 2);

    float acc[2][8][4];
#pragma unroll
    for (int mi = 0; mi < 2; mi++)
#pragma unroll
        for (int ni = 0; ni < 8; ni++)
#pragma unroll
            for (int j = 0; j < 4; j++) acc[mi][ni][j] = 0.f;

    gemm_core(A, W, sm, m0, n0, acc);

    const int wid = threadIdx.x >> 5, lane = threadIdx.x & 31;
    const int mw0 = (wid >> 1) * 32, nw0 = (wid & 1) * 64;
    const int r = lane >> 2, cq = lane & 3;
#pragma unroll
    for (int mi = 0; mi < 2; mi++){
#pragma unroll
        for (int ni = 0; ni < 8; ni++){
            const int row = m0 + mw0 + mi*16 + r;
            const int col = n0 + nw0 + ni*8 + cq*2;
            float v[4];
#pragma unroll
            for (int j = 0; j < 4; j++){
                float x = acc[mi][ni][j];
                if (act) x = (x > 0.f) ? (x + 1.f) : expf(x);
                v[j] = x;
            }
            float2 lo = {v[0], v[1]}, hi = {v[2], v[3]};
            *(float2*)&C[(size_t)row * E_ + col]     = lo;
            *(float2*)&C[(size_t)(row+8) * E_ + col] = hi;
        }
    }
}

// output projection with bias
__global__ __launch_bounds__(256)
void tc_gemm_out(const float* __restrict__ A, const float* __restrict__ W,
                 const float* __restrict__ bias, float* __restrict__ C)
{
    extern __shared__ float sm[];
    const int m0 = blockIdx.y * TM, n0 = blockIdx.x * TN;

    float acc[2][8][4];
#pragma unroll
    for (int mi = 0; mi < 2; mi++)
#pragma unroll
        for (int ni = 0; ni < 8; ni++)
#pragma unroll
            for (int j = 0; j < 4; j++) acc[mi][ni][j] = 0.f;

    gemm_core(A, W, sm, m0, n0, acc);

    const int wid = threadIdx.x >> 5, lane = threadIdx.x & 31;
    const int mw0 = (wid >> 1) * 32, nw0 = (wid & 1) * 64;
    const int r = lane >> 2, cq = lane & 3;
#pragma unroll
    for (int mi = 0; mi < 2; mi++){
#pragma unroll
        for (int ni = 0; ni < 8; ni++){
            const int row = m0 + mw0 + mi*16 + r;
            const int col = n0 + nw0 + ni*8 + cq*2;
            float b0 = bias[col], b1 = bias[col+1];
            float2 lo = {acc[mi][ni][0] + b0, acc[mi][ni][1] + b1};
            float2 hi = {acc[mi][ni][2] + b0, acc[mi][ni][3] + b1};
            *(float2*)&C[(size_t)row * E_ + col]     = lo;
            *(float2*)&C[(size_t)(row+8) * E_ + col] = hi;
        }
    }
}

// =================================================================
// kv/zk per chunk: kv[d,e] = sum_c phi_k[c,d]*v[c,e]; zk[d]=sum_c phi_k[c,d]
// =================================================================
__global__ __launch_bounds__(256)
void kv_kernel(const float* __restrict__ k, const float* __restrict__ v,
               float* __restrict__ kv, float* __restrict__ zk)
{
    extern __shared__ float sm[];
    float* sk = sm;              // 128*68
    float* sv = sm + 128*68;     // 128*68

    const int bid = blockIdx.x;
    const int n = bid % NC;
    const int h = (bid / NC) % H_;
    const int b = bid / (NC * H_);
    const int tid = threadIdx.x;

    const float* kb = k + (size_t)(b*T_ + n*CH) * E_ + h*D_;
    const float* vb = v + (size_t)(b*T_ + n*CH) * E_ + h*D_;

#pragma unroll
    for (int it = 0; it < 8; it++) {
        int idx4 = tid + it * 256;
        int c  = idx4 >> 4;
        int d0 = (idx4 & 15) << 2;
        *(float4*)&sk[c*68 + d0] = *(const float4*)&kb[(size_t)c * E_ + d0];
        *(float4*)&sv[c*68 + d0] = *(const float4*)&vb[(size_t)c * E_ + d0];
    }
    __syncthreads();

    const int tx = tid & 15, ty = tid >> 4;
    float acc[4][4];
#pragma unroll
    for (int i = 0; i < 4; i++)
#pragma unroll
        for (int j = 0; j < 4; j++) acc[i][j] = 0.f;

#pragma unroll 8
    for (int c = 0; c < 128; c++) {
        float4 kf = *(const float4*)&sk[c*68 + ty*4];
        float4 vf = *(const float4*)&sv[c*68 + tx*4];
        float ka[4] = {kf.x, kf.y, kf.z, kf.w};
        float va[4] = {vf.x, vf.y, vf.z, vf.w};
#pragma unroll
        for (int i = 0; i < 4; i++)
#pragma unroll
            for (int j = 0; j < 4; j++)
                acc[i][j] += ka[i] * va[j];
    }

    float* kvb = kv + (size_t)bid * (D_*D_);
#pragma unroll
    for (int i = 0; i < 4; i++) {
        float4 o = {acc[i][0], acc[i][1], acc[i][2], acc[i][3]};
        *(float4*)&kvb[(ty*4 + i) * D_ + tx*4] = o;
    }

    if (tid < D_) {
        float s = 0.f;
        for (int c = 0; c < 128; c++) s += sk[c*68 + tid];
        zk[(size_t)bid * D_ + tid] = s;
    }
}

// =================================================================
// exclusive prefix over chunks (N=16) per (b,h)
// =================================================================
__global__ __launch_bounds__(256)
void prefix_kernel(const float* __restrict__ kv, const float* __restrict__ zk,
                   float* __restrict__ S, float* __restrict__ Z)
{
    const int bh = blockIdx.x;
    const size_t base = (size_t)bh * NC * (D_*D_);
    for (int i = threadIdx.x; i < D_*D_; i += blockDim.x) {
        float run = 0.f;
        for (int n = 0; n < NC; n++) {
            S[base + (size_t)n * (D_*D_) + i] = run;
            run += kv[base + (size_t)n * (D_*D_) + i];
        }
    }
    const size_t zb = (size_t)bh * NC * D_;
    for (int i = threadIdx.x; i < D_; i += blockDim.x) {
        float run = 0.f;
        for (int n = 0; n < NC; n++) {
            Z[zb + (size_t)n * D_ + i] = run;
            run += zk[zb + (size_t)n * D_ + i];
        }
    }
}

// =================================================================
// intra-chunk attention (unchanged, passing)
// =================================================================
#define ATTN_SMEM_FLOATS 38336
__global__ __launch_bounds__(256)
void attn_kernel(const float* __restrict__ q, const float* __restrict__ k,
                 const float* __restrict__ v, const float* __restrict__ S,
                 const float* __restrict__ Z, float* __restrict__ y)
{
    extern __shared__ float sm[];
    float* sqT  = sm;
    float* skv  = sm + 8192;
    float* sAT  = sm + 16896;
    float* sS   = sm + 33792;
    float* sZ   = sm + 38144;
    float* sden = sm + 38208;

    const int bid = blockIdx.x;
    const int n = bid % NC;
    const int h = (bid / NC) % H_;
    const int b = bid / (NC * H_);
    const int tid = threadIdx.x, tx = tid & 15, ty = tid >> 4;

    const float* qb = q + (size_t)(b*T_ + n*CH) * E_ + h*D_;
    const float* kb = k + (size_t)(b*T_ + n*CH) * E_ + h*D_;
    const float* vb = v + (size_t)(b*T_ + n*CH) * E_ + h*D_;
    const float* Sb = S + (size_t)bid * (D_*D_);
    const float* Zb = Z + (size_t)bid * D_;

#pragma unroll
    for (int it = 0; it < 8; it++) {
        int idx4 = tid + it * 256;
        int c  = idx4 >> 4;
        int d0 = (idx4 & 15) << 2;
        float4 vq = *(const float4*)&qb[(size_t)c * E_ + d0];
        sqT[(d0+0)*128 + c] = vq.x;
        sqT[(d0+1)*128 + c] = vq.y;
        sqT[(d0+2)*128 + c] = vq.z;
        sqT[(d0+3)*128 + c] = vq.w;
        float4 vk = *(const float4*)&kb[(size_t)c * E_ + d0];
        skv[(d0+0)*128 + c] = vk.x;
        skv[(d0+1)*128 + c] = vk.y;
        skv[(d0+2)*128 + c] = vk.z;
        skv[(d0+3)*128 + c] = vk.w;
    }
    __syncthreads();

    float acc[8][8];
#pragma unroll
    for (int i = 0; i < 8; i++)
#pragma unroll
        for (int j = 0; j < 8; j++) acc[i][j] = 0.f;

#pragma unroll 8
    for (int kk = 0; kk < 64; kk++) {
        float af[8], bf[8];
        *(float4*)&af[0] = *(const float4*)&sqT[kk*128 + ty*8];
        *(float4*)&af[4] = *(const float4*)&sqT[kk*128 + ty*8 + 4];
        *(float4*)&bf[0] = *(const float4*)&skv[kk*128 + tx*8];
        *(float4*)&bf[4] = *(const float4*)&skv[kk*128 + tx*8 + 4];
#pragma unroll
        for (int i = 0; i < 8; i++)
#pragma unroll
            for (int j = 0; j < 8; j++)
                acc[i][j] += af[i] * bf[j];
    }

    const int c0 = ty*8, s0 = tx*8;
#pragma unroll
    for (int j = 0; j < 8; j++) {
        int s = s0 + j;
#pragma unroll
        for (int i = 0; i < 8; i++)
            if (s > c0 + i) acc[i][j] = 0.f;
        float4 t0 = {acc[0][j], acc[1][j], acc[2][j], acc[3][j]};
        *(float4*)&sAT[s*132 + c0] = t0;
        float4 t1 = {acc[4][j], acc[5][j], acc[6][j], acc[7][j]};
        *(float4*)&sAT[s*132 + c0 + 4] = t1;
    }
    __syncthreads();

#pragma unroll
    for (int it = 0; it < 8; it++) {
        int idx4 = tid + it * 256;
        int c  = idx4 >> 4;
        int e0 = (idx4 & 15) << 2;
        *(float4*)&skv[c*68 + e0] = *(const float4*)&vb[(size_t)c * E_ + e0];
    }
#pragma unroll
    for (int it = 0; it < 4; it++) {
        int idx4 = tid + it * 256;
        int d  = idx4 >> 4;
        int e0 = (idx4 & 15) << 2;
        *(float4*)&sS[d*68 + e0] = *(const float4*)&Sb[d*D_ + e0];
    }
    if (tid < 16)
        *(float4*)&sZ[tid*4] = *(const float4*)&Zb[tid*4];
    __syncthreads();

    if (tid < 128) {
        float s = EPS;
        for (int ss = 0; ss < 128; ss++) s += sAT[ss*132 + tid];
        for (int d = 0; d < 64; d++)     s += sqT[d*128 + tid] * sZ[d];
        sden[tid] = s;
    }
    __syncthreads();

    float num[8][4];
#pragma unroll
    for (int i = 0; i < 8; i++)
#pragma unroll
        for (int j = 0; j < 4; j++) num[i][j] = 0.f;

#pragma unroll 8
    for (int ss = 0; ss < 128; ss++) {
        float af[8];
        *(float4*)&af[0] = *(const float4*)&sAT[ss*132 + ty*8];
        *(float4*)&af[4] = *(const float4*)&sAT[ss*132 + ty*8 + 4];
        float4 vf = *(const float4*)&skv[ss*68 + tx*4];
        float vv[4] = {vf.x, vf.y, vf.z, vf.w};
#pragma unroll
        for (int i = 0; i < 8; i++)
#pragma unroll
            for (int j = 0; j < 4; j++)
                num[i][j] += af[i] * vv[j];
    }
#pragma unroll 8
    for (int d = 0; d < 64; d++) {
        float af[8];
        *(float4*)&af[0] = *(const float4*)&sqT[d*128 + ty*8];
        *(float4*)&af[4] = *(const float4*)&sqT[d*128 + ty*8 + 4];
        float4 sf = *(const float4*)&sS[d*68 + tx*4];
        float svv[4] = {sf.x, sf.y, sf.z, sf.w};
#pragma unroll
        for (int i = 0; i < 8; i++)
#pragma unroll
            for (int j = 0; j < 4; j++)
                num[i][j] += af[i] * svv[j];
    }

    float* yb = y + (size_t)(b*T_ + n*CH) * E_ + h*D_;
#pragma unroll
    for (int i = 0; i < 8; i++) {
        int c = ty*8 + i;
        float inv = 1.f / sden[c];
        float4 o = {num[i][0]*inv, num[i][1]*inv, num[i][2]*inv, num[i][3]*inv};
        *(float4*)&yb[(size_t)c * E_ + tx*4] = o;
    }
}

// =================================================================
extern "C" void kernel_launch(void* const* d_in, const int* in_sizes, int n_in,
                              void* d_out, int out_size)
{
    const float* x  = (const float*)d_in[0];
    const float* Wq = (const float*)d_in[1];
    const float* Wk = (const float*)d_in[2];
    const float* Wv = (const float*)d_in[3];
    const float* Wp = (const float*)d_in[4];
    const float* bp = (const float*)d_in[5];
    float* out = (float*)d_out;

    float *q, *k, *v, *y, *xc, *wqc, *wkc, *wvc, *wpc, *kv, *zk, *S, *Z;
    cudaGetSymbolAddress((void**)&q,   g_q);
    cudaGetSymbolAddress((void**)&k,   g_k);
    cudaGetSymbolAddress((void**)&v,   g_v);
    cudaGetSymbolAddress((void**)&y,   g_y);
    cudaGetSymbolAddress((void**)&xc,  g_xc);
    cudaGetSymbolAddress((void**)&wqc, g_wqc);
    cudaGetSymbolAddress((void**)&wkc, g_wkc);
    cudaGetSymbolAddress((void**)&wvc, g_wvc);
    cudaGetSymbolAddress((void**)&wpc, g_wpc);
    cudaGetSymbolAddress((void**)&kv,  g_kv);
    cudaGetSymbolAddress((void**)&zk,  g_zk);
    cudaGetSymbolAddress((void**)&S,   g_S);
    cudaGetSymbolAddress((void**)&Z,   g_Z);

    const int kv_smem   = 2 * 128 * 68 * (int)sizeof(float);
    const int attn_smem = ATTN_SMEM_FLOATS * (int)sizeof(float);
    cudaFuncSetAttribute(kv_kernel,   cudaFuncAttributeMaxDynamicSharedMemorySize, kv_smem);
    cudaFuncSetAttribute(attn_kernel, cudaFuncAttributeMaxDynamicSharedMemorySize, attn_smem);
    cudaFuncSetAttribute(tc_gemm_qkv, cudaFuncAttributeMaxDynamicSharedMemorySize, GEMM_SMEM);
    cudaFuncSetAttribute(tc_gemm_out, cudaFuncAttributeMaxDynamicSharedMemorySize, GEMM_SMEM);

    dim3 blk(256);

    // one-time tf32 rounding + k-permutation of GEMM inputs
    convert_perm<<<(M_*E_)/256, blk>>>(x,  xc,  M_*E_);
    convert_perm<<<(E_*E_)/256, blk>>>(Wq, wqc, E_*E_);
    convert_perm<<<(E_*E_)/256, blk>>>(Wk, wkc, E_*E_);
    convert_perm<<<(E_*E_)/256, blk>>>(Wv, wvc, E_*E_);
    convert_perm<<<(E_*E_)/256, blk>>>(Wp, wpc, E_*E_);

    tc_gemm_qkv<<<dim3(24, M_/TM), blk, GEMM_SMEM>>>(xc, wqc, wkc, wvc, q, k, v);

    kv_kernel<<<B_*H_*NC, blk, kv_smem>>>(k, v, kv, zk);
    prefix_kernel<<<B_*H_, blk>>>(kv, zk, S, Z);
    attn_kernel<<<B_*H_*NC, blk, attn_smem>>>(q, k, v, S, Z, y);

    convert_perm<<<(M_*E_)/256, blk>>>(y, xc, M_*E_);   // reuse xc for y
    tc_gemm_out<<<dim3(8, M_/TM), blk, GEMM_SMEM>>>(xc, wpc, bp, out);
}

// round 9
// speedup vs baseline: 1.1438x; 1.1438x over previous
#include <cuda_runtime.h>
#include <cuda_fp16.h>
#include <math.h>
#include <stdint.h>

#define B_  4
#define T_  2048
#define E_  1024
#define H_  16
#define D_  64
#define CH  128
#define NC  (T_/CH)      // 16
#define M_  (B_*T_)      // 8192
#define EPS 1e-6f

// ---------------- scratch (no allocations allowed) ----------------
__device__ float  g_q[M_*E_];
__device__ float  g_k[M_*E_];
__device__ float  g_v[M_*E_];
__device__ __half g_xh[M_*E_];
__device__ __half g_yh[M_*E_];
__device__ __half g_wh[4*E_*E_];    // Wq, Wk, Wv, Wp
__device__ float  g_kv[B_*H_*NC*D_*D_];
__device__ float  g_zk[B_*H_*NC*D_];
__device__ float  g_S [B_*H_*NC*D_*D_];
__device__ float  g_Z [B_*H_*NC*D_];

// =================================================================
// helpers
// =================================================================
__device__ __forceinline__ uint32_t smem_u32(const void* p){
    uint32_t a;
    asm("{ .reg .u64 t; cvta.to.shared.u64 t, %1; cvt.u32.u64 %0, t; }" : "=r"(a) : "l"(p));
    return a;
}
__device__ __forceinline__ void cpasync16(uint32_t dst, const void* src){
    asm volatile("cp.async.cg.shared.global [%0], [%1], 16;" :: "r"(dst), "l"(src));
}
__device__ __forceinline__ void cp_commit(){ asm volatile("cp.async.commit_group;" ::: "memory"); }
__device__ __forceinline__ void cp_wait1(){ asm volatile("cp.async.wait_group 1;" ::: "memory"); }

__device__ __forceinline__ void mma_f16_16x8x16(float* c, const uint32_t* a, const uint32_t* b){
    asm volatile(
        "mma.sync.aligned.m16n8k16.row.col.f32.f16.f16.f32 "
        "{%0,%1,%2,%3}, {%4,%5,%6,%7}, {%8,%9}, {%0,%1,%2,%3};"
        : "+f"(c[0]), "+f"(c[1]), "+f"(c[2]), "+f"(c[3])
        : "r"(a[0]), "r"(a[1]), "r"(a[2]), "r"(a[3]), "r"(b[0]), "r"(b[1]));
}

// =================================================================
// float -> half conversion (coalesced, 8 elems/thread)
// =================================================================
__global__ __launch_bounds__(256)
void f2h_kernel(const float* __restrict__ in, __half* __restrict__ out, int n){
    int i = (blockIdx.x * 256 + threadIdx.x) * 8;
    if (i >= n) return;
    float4 v0 = *(const float4*)&in[i];
    float4 v1 = *(const float4*)&in[i+4];
    __half2 h[4];
    h[0] = __floats2half2_rn(v0.x, v0.y);
    h[1] = __floats2half2_rn(v0.z, v0.w);
    h[2] = __floats2half2_rn(v1.x, v1.y);
    h[3] = __floats2half2_rn(v1.z, v1.w);
    *(uint4*)&out[i] = *(uint4*)h;
}

// =================================================================
// fp16 mma.sync GEMM core: C = A[m,k] * W[n,k]^T, fp32 accum.
// tile 128x128, K chunks of 64 halves (=128B rows), 3-stage cp.async.
// 8 warps as 4(m) x 2(n); warp tile 32x64 -> 2 m-frags x 8 n-frags.
// ROWH=72 halves padding -> conflict-free 32-bit fragment loads.
// =================================================================
#define TM 128
#define TN 128
#define TKH 64                             // k per chunk (halves)
#define NS 3
#define NCHUNK (E_/TKH)                    // 16
#define ROWH 72                            // padded row stride (halves)
#define TILE_H (128*ROWH)                  // halves per tile
#define STAGE_H (2*TILE_H)
#define GEMM_SMEM (NS*STAGE_H*2)           // 110592 bytes

__device__ __forceinline__ void load_chunk_h(const __half* __restrict__ A,
                                             const __half* __restrict__ W,
                                             int m0, int n0, int k0,
                                             uint32_t sA, uint32_t sW, int tid){
#pragma unroll
    for (int it = 0; it < 4; it++){
        int idx = tid + it*256;            // 0..1023
        int row = idx >> 3;                // 0..127
        int g   = idx & 7;                 // 16B granule within 128B row
        uint32_t soff = row*(ROWH*2) + g*16;
        cpasync16(sA + soff, A + (size_t)(m0+row)*E_ + k0 + g*8);
        cpasync16(sW + soff, W + (size_t)(n0+row)*E_ + k0 + g*8);
    }
}

__device__ __forceinline__ void gemm_core_h(const __half* __restrict__ A,
                                            const __half* __restrict__ W,
                                            __half* smh, int m0, int n0,
                                            float acc[2][8][4]){
    const int tid = threadIdx.x;
    const int wid = tid >> 5, lane = tid & 31;
    const int mw0 = (wid >> 1) * 32;
    const int nw0 = (wid & 1) * 64;
    const int r   = lane >> 2;             // groupID 0..7
    const int tig = lane & 3;              // 0..3
    const uint32_t sb = smem_u32(smh);

#pragma unroll
    for (int c = 0; c < NS-1; c++){
        uint32_t st = sb + c*STAGE_H*2;
        load_chunk_h(A, W, m0, n0, c*TKH, st, st + TILE_H*2, tid);
        cp_commit();
    }

    for (int c = 0; c < NCHUNK; c++){
        cp_wait1();
        __syncthreads();
        if (c + 2 < NCHUNK){
            uint32_t st = sb + ((c+2)%NS)*STAGE_H*2;
            load_chunk_h(A, W, m0, n0, (c+2)*TKH, st, st + TILE_H*2, tid);
        }
        cp_commit();

        const __half* fa = smh + (c%NS)*STAGE_H;
        const __half* fw = fa + TILE_H;

#pragma unroll
        for (int ks = 0; ks < 4; ks++){
            const int kb = ks*16 + tig*2;
            uint32_t afr[2][4];
#pragma unroll
            for (int mi = 0; mi < 2; mi++){
                const __half* ap = fa + (mw0 + mi*16 + r)*ROWH + kb;
                afr[mi][0] = *(const uint32_t*)ap;             // (row, k..k+1)
                afr[mi][1] = *(const uint32_t*)(ap + 8*ROWH);  // (row+8)
                afr[mi][2] = *(const uint32_t*)(ap + 8);       // (row, k+8..9)
                afr[mi][3] = *(const uint32_t*)(ap + 8*ROWH + 8);
            }
#pragma unroll
            for (int ni = 0; ni < 8; ni++){
                const __half* bp = fw + (nw0 + ni*8 + r)*ROWH + kb;
                uint32_t bfr[2];
                bfr[0] = *(const uint32_t*)bp;
                bfr[1] = *(const uint32_t*)(bp + 8);
#pragma unroll
                for (int mi = 0; mi < 2; mi++)
                    mma_f16_16x8x16(acc[mi][ni], afr[mi], bfr);
            }
        }
        __syncthreads();
    }
}

// fused q/k/v projection: blockIdx.x in [0,24): which = x>>3
__global__ __launch_bounds__(256)
void tc_gemm_qkv(const __half* __restrict__ A, const __half* __restrict__ Wh,
                 float* __restrict__ C0, float* __restrict__ C1,
                 float* __restrict__ C2)
{
    extern __shared__ __half smh[];
    const int which = blockIdx.x >> 3;
    const int m0 = blockIdx.y * TM, n0 = (blockIdx.x & 7) * TN;
    const __half* W = Wh + (size_t)which * E_ * E_;
    float* C = (which == 0) ? C0 : (which == 1) ? C1 : C2;
    const bool act = (which < 2);

    float acc[2][8][4];
#pragma unroll
    for (int mi = 0; mi < 2; mi++)
#pragma unroll
        for (int ni = 0; ni < 8; ni++)
#pragma unroll
            for (int j = 0; j < 4; j++) acc[mi][ni][j] = 0.f;

    gemm_core_h(A, W, smh, m0, n0, acc);

    const int wid = threadIdx.x >> 5, lane = threadIdx.x & 31;
    const int mw0 = (wid >> 1) * 32, nw0 = (wid & 1) * 64;
    const int r = lane >> 2, tig = lane & 3;
#pragma unroll
    for (int mi = 0; mi < 2; mi++){
#pragma unroll
        for (int ni = 0; ni < 8; ni++){
            const int row = m0 + mw0 + mi*16 + r;
            const int col = n0 + nw0 + ni*8 + tig*2;
            float v[4];
#pragma unroll
            for (int j = 0; j < 4; j++){
                float x = acc[mi][ni][j];
                if (act) x = (x > 0.f) ? (x + 1.f) : expf(x);
                v[j] = x;
            }
            float2 lo = {v[0], v[1]}, hi = {v[2], v[3]};
            *(float2*)&C[(size_t)row * E_ + col]     = lo;
            *(float2*)&C[(size_t)(row+8) * E_ + col] = hi;
        }
    }
}

// output projection with bias
__global__ __launch_bounds__(256)
void tc_gemm_out(const __half* __restrict__ A, const __half* __restrict__ Wh,
                 const float* __restrict__ bias, float* __restrict__ C)
{
    extern __shared__ __half smh[];
    const int m0 = blockIdx.y * TM, n0 = blockIdx.x * TN;
    const __half* W = Wh + (size_t)3 * E_ * E_;

    float acc[2][8][4];
#pragma unroll
    for (int mi = 0; mi < 2; mi++)
#pragma unroll
        for (int ni = 0; ni < 8; ni++)
#pragma unroll
            for (int j = 0; j < 4; j++) acc[mi][ni][j] = 0.f;

    gemm_core_h(A, W, smh, m0, n0, acc);

    const int wid = threadIdx.x >> 5, lane = threadIdx.x & 31;
    const int mw0 = (wid >> 1) * 32, nw0 = (wid & 1) * 64;
    const int r = lane >> 2, tig = lane & 3;
#pragma unroll
    for (int mi = 0; mi < 2; mi++){
#pragma unroll
        for (int ni = 0; ni < 8; ni++){
            const int row = m0 + mw0 + mi*16 + r;
            const int col = n0 + nw0 + ni*8 + tig*2;
            float b0 = bias[col], b1 = bias[col+1];
            float2 lo = {acc[mi][ni][0] + b0, acc[mi][ni][1] + b1};
            float2 hi = {acc[mi][ni][2] + b0, acc[mi][ni][3] + b1};
            *(float2*)&C[(size_t)row * E_ + col]     = lo;
            *(float2*)&C[(size_t)(row+8) * E_ + col] = hi;
        }
    }
}

// =================================================================
// kv/zk per chunk: kv[d,e] = sum_c phi_k[c,d]*v[c,e]; zk[d]=sum_c phi_k[c,d]
// =================================================================
__global__ __launch_bounds__(256)
void kv_kernel(const float* __restrict__ k, const float* __restrict__ v,
               float* __restrict__ kv, float* __restrict__ zk)
{
    extern __shared__ float sm[];
    float* sk = sm;              // 128*68
    float* sv = sm + 128*68;     // 128*68

    const int bid = blockIdx.x;
    const int n = bid % NC;
    const int h = (bid / NC) % H_;
    const int b = bid / (NC * H_);
    const int tid = threadIdx.x;

    const float* kb = k + (size_t)(b*T_ + n*CH) * E_ + h*D_;
    const float* vb = v + (size_t)(b*T_ + n*CH) * E_ + h*D_;

#pragma unroll
    for (int it = 0; it < 8; it++) {
        int idx4 = tid + it * 256;
        int c  = idx4 >> 4;
        int d0 = (idx4 & 15) << 2;
        *(float4*)&sk[c*68 + d0] = *(const float4*)&kb[(size_t)c * E_ + d0];
        *(float4*)&sv[c*68 + d0] = *(const float4*)&vb[(size_t)c * E_ + d0];
    }
    __syncthreads();

    const int tx = tid & 15, ty = tid >> 4;
    float acc[4][4];
#pragma unroll
    for (int i = 0; i < 4; i++)
#pragma unroll
        for (int j = 0; j < 4; j++) acc[i][j] = 0.f;

#pragma unroll 8
    for (int c = 0; c < 128; c++) {
        float4 kf = *(const float4*)&sk[c*68 + ty*4];
        float4 vf = *(const float4*)&sv[c*68 + tx*4];
        float ka[4] = {kf.x, kf.y, kf.z, kf.w};
        float va[4] = {vf.x, vf.y, vf.z, vf.w};
#pragma unroll
        for (int i = 0; i < 4; i++)
#pragma unroll
            for (int j = 0; j < 4; j++)
                acc[i][j] += ka[i] * va[j];
    }

    float* kvb = kv + (size_t)bid * (D_*D_);
#pragma unroll
    for (int i = 0; i < 4; i++) {
        float4 o = {acc[i][0], acc[i][1], acc[i][2], acc[i][3]};
        *(float4*)&kvb[(ty*4 + i) * D_ + tx*4] = o;
    }

    if (tid < D_) {
        float s = 0.f;
        for (int c = 0; c < 128; c++) s += sk[c*68 + tid];
        zk[(size_t)bid * D_ + tid] = s;
    }
}

// =================================================================
// exclusive prefix over chunks (N=16) per (b,h)
// =================================================================
__global__ __launch_bounds__(256)
void prefix_kernel(const float* __restrict__ kv, const float* __restrict__ zk,
                   float* __restrict__ S, float* __restrict__ Z)
{
    const int bh = blockIdx.x;
    const size_t base = (size_t)bh * NC * (D_*D_);
    for (int i = threadIdx.x; i < D_*D_; i += blockDim.x) {
        float run = 0.f;
        for (int n = 0; n < NC; n++) {
            S[base + (size_t)n * (D_*D_) + i] = run;
            run += kv[base + (size_t)n * (D_*D_) + i];
        }
    }
    const size_t zb = (size_t)bh * NC * D_;
    for (int i = threadIdx.x; i < D_; i += blockDim.x) {
        float run = 0.f;
        for (int n = 0; n < NC; n++) {
            Z[zb + (size_t)n * D_ + i] = run;
            run += zk[zb + (size_t)n * D_ + i];
        }
    }
}

// =================================================================
// intra-chunk attention (fp32 math; writes y as fp16 for final GEMM)
// =================================================================
#define ATTN_SMEM_FLOATS 38336
__global__ __launch_bounds__(256)
void attn_kernel(const float* __restrict__ q, const float* __restrict__ k,
                 const float* __restrict__ v, const float* __restrict__ S,
                 const float* __restrict__ Z, __half* __restrict__ y)
{
    extern __shared__ float sm[];
    float* sqT  = sm;
    float* skv  = sm + 8192;
    float* sAT  = sm + 16896;
    float* sS   = sm + 33792;
    float* sZ   = sm + 38144;
    float* sden = sm + 38208;

    const int bid = blockIdx.x;
    const int n = bid % NC;
    const int h = (bid / NC) % H_;
    const int b = bid / (NC * H_);
    const int tid = threadIdx.x, tx = tid & 15, ty = tid >> 4;

    const float* qb = q + (size_t)(b*T_ + n*CH) * E_ + h*D_;
    const float* kb = k + (size_t)(b*T_ + n*CH) * E_ + h*D_;
    const float* vb = v + (size_t)(b*T_ + n*CH) * E_ + h*D_;
    const float* Sb = S + (size_t)bid * (D_*D_);
    const float* Zb = Z + (size_t)bid * D_;

#pragma unroll
    for (int it = 0; it < 8; it++) {
        int idx4 = tid + it * 256;
        int c  = idx4 >> 4;
        int d0 = (idx4 & 15) << 2;
        float4 vq = *(const float4*)&qb[(size_t)c * E_ + d0];
        sqT[(d0+0)*128 + c] = vq.x;
        sqT[(d0+1)*128 + c] = vq.y;
        sqT[(d0+2)*128 + c] = vq.z;
        sqT[(d0+3)*128 + c] = vq.w;
        float4 vk = *(const float4*)&kb[(size_t)c * E_ + d0];
        skv[(d0+0)*128 + c] = vk.x;
        skv[(d0+1)*128 + c] = vk.y;
        skv[(d0+2)*128 + c] = vk.z;
        skv[(d0+3)*128 + c] = vk.w;
    }
    __syncthreads();

    float acc[8][8];
#pragma unroll
    for (int i = 0; i < 8; i++)
#pragma unroll
        for (int j = 0; j < 8; j++) acc[i][j] = 0.f;

#pragma unroll 8
    for (int kk = 0; kk < 64; kk++) {
        float af[8], bf[8];
        *(float4*)&af[0] = *(const float4*)&sqT[kk*128 + ty*8];
        *(float4*)&af[4] = *(const float4*)&sqT[kk*128 + ty*8 + 4];
        *(float4*)&bf[0] = *(const float4*)&skv[kk*128 + tx*8];
        *(float4*)&bf[4] = *(const float4*)&skv[kk*128 + tx*8 + 4];
#pragma unroll
        for (int i = 0; i < 8; i++)
#pragma unroll
            for (int j = 0; j < 8; j++)
                acc[i][j] += af[i] * bf[j];
    }

    const int c0 = ty*8, s0 = tx*8;
#pragma unroll
    for (int j = 0; j < 8; j++) {
        int s = s0 + j;
#pragma unroll
        for (int i = 0; i < 8; i++)
            if (s > c0 + i) acc[i][j] = 0.f;
        float4 t0 = {acc[0][j], acc[1][j], acc[2][j], acc[3][j]};
        *(float4*)&sAT[s*132 + c0] = t0;
        float4 t1 = {acc[4][j], acc[5][j], acc[6][j], acc[7][j]};
        *(float4*)&sAT[s*132 + c0 + 4] = t1;
    }
    __syncthreads();

#pragma unroll
    for (int it = 0; it < 8; it++) {
        int idx4 = tid + it * 256;
        int c  = idx4 >> 4;
        int e0 = (idx4 & 15) << 2;
        *(float4*)&skv[c*68 + e0] = *(const float4*)&vb[(size_t)c * E_ + e0];
    }
#pragma unroll
    for (int it = 0; it < 4; it++) {
        int idx4 = tid + it * 256;
        int d  = idx4 >> 4;
        int e0 = (idx4 & 15) << 2;
        *(float4*)&sS[d*68 + e0] = *(const float4*)&Sb[d*D_ + e0];
    }
    if (tid < 16)
        *(float4*)&sZ[tid*4] = *(const float4*)&Zb[tid*4];
    __syncthreads();

    if (tid < 128) {
        float s = EPS;
        for (int ss = 0; ss < 128; ss++) s += sAT[ss*132 + tid];
        for (int d = 0; d < 64; d++)     s += sqT[d*128 + tid] * sZ[d];
        sden[tid] = s;
    }
    __syncthreads();

    float num[8][4];
#pragma unroll
    for (int i = 0; i < 8; i++)
#pragma unroll
        for (int j = 0; j < 4; j++) num[i][j] = 0.f;

#pragma unroll 8
    for (int ss = 0; ss < 128; ss++) {
        float af[8];
        *(float4*)&af[0] = *(const float4*)&sAT[ss*132 + ty*8];
        *(float4*)&af[4] = *(const float4*)&sAT[ss*132 + ty*8 + 4];
        float4 vf = *(const float4*)&skv[ss*68 + tx*4];
        float vv[4] = {vf.x, vf.y, vf.z, vf.w};
#pragma unroll
        for (int i = 0; i < 8; i++)
#pragma unroll
            for (int j = 0; j < 4; j++)
                num[i][j] += af[i] * vv[j];
    }
#pragma unroll 8
    for (int d = 0; d < 64; d++) {
        float af[8];
        *(float4*)&af[0] = *(const float4*)&sqT[d*128 + ty*8];
        *(float4*)&af[4] = *(const float4*)&sqT[d*128 + ty*8 + 4];
        float4 sf = *(const float4*)&sS[d*68 + tx*4];
        float svv[4] = {sf.x, sf.y, sf.z, sf.w};
#pragma unroll
        for (int i = 0; i < 8; i++)
#pragma unroll
            for (int j = 0; j < 4; j++)
                num[i][j] += af[i] * svv[j];
    }

    __half* yb = y + (size_t)(b*T_ + n*CH) * E_ + h*D_;
#pragma unroll
    for (int i = 0; i < 8; i++) {
        int c = ty*8 + i;
        float inv = 1.f / sden[c];
        __half2 h0 = __floats2half2_rn(num[i][0]*inv, num[i][1]*inv);
        __half2 h1 = __floats2half2_rn(num[i][2]*inv, num[i][3]*inv);
        uint2 o = {*(uint32_t*)&h0, *(uint32_t*)&h1};
        *(uint2*)&yb[(size_t)c * E_ + tx*4] = o;
    }
}

// =================================================================
extern "C" void kernel_launch(void* const* d_in, const int* in_sizes, int n_in,
                              void* d_out, int out_size)
{
    const float* x  = (const float*)d_in[0];
    const float* Wq = (const float*)d_in[1];
    const float* Wk = (const float*)d_in[2];
    const float* Wv = (const float*)d_in[3];
    const float* Wp = (const float*)d_in[4];
    const float* bp = (const float*)d_in[5];
    float* out = (float*)d_out;

    float *q, *k, *v, *kv, *zk, *S, *Z;
    __half *xh, *yh, *wh;
    cudaGetSymbolAddress((void**)&q,  g_q);
    cudaGetSymbolAddress((void**)&k,  g_k);
    cudaGetSymbolAddress((void**)&v,  g_v);
    cudaGetSymbolAddress((void**)&xh, g_xh);
    cudaGetSymbolAddress((void**)&yh, g_yh);
    cudaGetSymbolAddress((void**)&wh, g_wh);
    cudaGetSymbolAddress((void**)&kv, g_kv);
    cudaGetSymbolAddress((void**)&zk, g_zk);
    cudaGetSymbolAddress((void**)&S,  g_S);
    cudaGetSymbolAddress((void**)&Z,  g_Z);

    const int kv_smem   = 2 * 128 * 68 * (int)sizeof(float);
    const int attn_smem = ATTN_SMEM_FLOATS * (int)sizeof(float);
    cudaFuncSetAttribute(kv_kernel,   cudaFuncAttributeMaxDynamicSharedMemorySize, kv_smem);
    cudaFuncSetAttribute(attn_kernel, cudaFuncAttributeMaxDynamicSharedMemorySize, attn_smem);
    cudaFuncSetAttribute(tc_gemm_qkv, cudaFuncAttributeMaxDynamicSharedMemorySize, GEMM_SMEM);
    cudaFuncSetAttribute(tc_gemm_out, cudaFuncAttributeMaxDynamicSharedMemorySize, GEMM_SMEM);

    dim3 blk(256);

    // one-time fp16 conversion of GEMM inputs
    f2h_kernel<<<(M_*E_)/2048, blk>>>(x,  xh, M_*E_);
    f2h_kernel<<<(E_*E_)/2048, blk>>>(Wq, wh + 0*(size_t)E_*E_, E_*E_);
    f2h_kernel<<<(E_*E_)/2048, blk>>>(Wk, wh + 1*(size_t)E_*E_, E_*E_);
    f2h_kernel<<<(E_*E_)/2048, blk>>>(Wv, wh + 2*(size_t)E_*E_, E_*E_);
    f2h_kernel<<<(E_*E_)/2048, blk>>>(Wp, wh + 3*(size_t)E_*E_, E_*E_);

    tc_gemm_qkv<<<dim3(24, M_/TM), blk, GEMM_SMEM>>>(xh, wh, q, k, v);

    kv_kernel<<<B_*H_*NC, blk, kv_smem>>>(k, v, kv, zk);
    prefix_kernel<<<B_*H_, blk>>>(kv, zk, S, Z);
    attn_kernel<<<B_*H_*NC, blk, attn_smem>>>(q, k, v, S, Z, yh);

    tc_gemm_out<<<dim3(8, M_/TM), blk, GEMM_SMEM>>>(yh, wh, bp, out);
}

// round 10
// speedup vs baseline: 1.6776x; 1.4667x over previous
#include <cuda_runtime.h>
#include <cuda_fp16.h>
#include <math.h>
#include <stdint.h>

#define B_  4
#define T_  2048
#define E_  1024
#define H_  16
#define D_  64
#define CH  128
#define NC  (T_/CH)      // 16
#define M_  (B_*T_)      // 8192
#define EPS 1e-6f

// ---------------- scratch (no allocations allowed) ----------------
__device__ float  g_q[M_*E_];
__device__ float  g_k[M_*E_];
__device__ float  g_v[M_*E_];
__device__ __half g_xh[M_*E_];
__device__ __half g_yh[M_*E_];
__device__ __half g_wh[4*E_*E_];    // Wq, Wk, Wv, Wp
__device__ float  g_kv[B_*H_*NC*D_*D_];
__device__ float  g_zk[B_*H_*NC*D_];
__device__ float  g_S [B_*H_*NC*D_*D_];
__device__ float  g_Z [B_*H_*NC*D_];

// =================================================================
// helpers
// =================================================================
__device__ __forceinline__ uint32_t smem_u32(const void* p){
    uint32_t a;
    asm("{ .reg .u64 t; cvta.to.shared.u64 t, %1; cvt.u32.u64 %0, t; }" : "=r"(a) : "l"(p));
    return a;
}
__device__ __forceinline__ void cpasync16(uint32_t dst, const void* src){
    asm volatile("cp.async.cg.shared.global [%0], [%1], 16;" :: "r"(dst), "l"(src));
}
__device__ __forceinline__ void cp_commit(){ asm volatile("cp.async.commit_group;" ::: "memory"); }
__device__ __forceinline__ void cp_wait2(){ asm volatile("cp.async.wait_group 2;" ::: "memory"); }

__device__ __forceinline__ void mma_f16_16x8x16(float* c, const uint32_t* a, const uint32_t* b){
    asm volatile(
        "mma.sync.aligned.m16n8k16.row.col.f32.f16.f16.f32 "
        "{%0,%1,%2,%3}, {%4,%5,%6,%7}, {%8,%9}, {%0,%1,%2,%3};"
        : "+f"(c[0]), "+f"(c[1]), "+f"(c[2]), "+f"(c[3])
        : "r"(a[0]), "r"(a[1]), "r"(a[2]), "r"(a[3]), "r"(b[0]), "r"(b[1]));
}
__device__ __forceinline__ void ldsm_x4(uint32_t* r, uint32_t addr){
    asm volatile("ldmatrix.sync.aligned.m8n8.x4.shared.b16 {%0,%1,%2,%3}, [%4];"
        : "=r"(r[0]), "=r"(r[1]), "=r"(r[2]), "=r"(r[3]) : "r"(addr));
}

// =================================================================
// float -> half conversion (coalesced, 8 elems/thread)
// =================================================================
__global__ __launch_bounds__(256)
void f2h_kernel(const float* __restrict__ in, __half* __restrict__ out, int n){
    int i = (blockIdx.x * 256 + threadIdx.x) * 8;
    if (i >= n) return;
    float4 v0 = *(const float4*)&in[i];
    float4 v1 = *(const float4*)&in[i+4];
    __half2 h[4];
    h[0] = __floats2half2_rn(v0.x, v0.y);
    h[1] = __floats2half2_rn(v0.z, v0.w);
    h[2] = __floats2half2_rn(v1.x, v1.y);
    h[3] = __floats2half2_rn(v1.z, v1.w);
    *(uint4*)&out[i] = *(uint4*)h;
}

// =================================================================
// fp16 mma.sync GEMM core: C = A[m,k] * W[n,k]^T, fp32 accum.
// tile 128x128, K chunks of 32 halves (=64B rows), 4-stage cp.async,
// ldmatrix.x4 fragment loads, 2 CTAs/SM.
// 8 warps as 4(m) x 2(n); warp tile 32x64 -> 2 m-frags x 8 n-frags.
// ROWH=40 halves padding (80B row stride -> conflict-free ldmatrix).
// =================================================================
#define TM 128
#define TN 128
#define TKH 32                             // k per chunk (halves)
#define NS 4
#define NCHUNK (E_/TKH)                    // 32
#define ROWH 40                            // padded row stride (halves)
#define TILE_H (128*ROWH)                  // 5120 halves
#define STAGE_H (2*TILE_H)
#define GEMM_SMEM (NS*STAGE_H*2)           // 81920 bytes

__device__ __forceinline__ void load_chunk_h(const __half* __restrict__ A,
                                             const __half* __restrict__ W,
                                             int m0, int n0, int k0,
                                             uint32_t sA, uint32_t sW, int tid){
#pragma unroll
    for (int it = 0; it < 2; it++){
        int idx = tid + it*256;            // 0..511
        int row = idx >> 2;                // 0..127
        int g   = idx & 3;                 // 16B granule within 64B row
        uint32_t soff = row*(ROWH*2) + g*16;
        cpasync16(sA + soff, A + (size_t)(m0+row)*E_ + k0 + g*8);
        cpasync16(sW + soff, W + (size_t)(n0+row)*E_ + k0 + g*8);
    }
}

__device__ __forceinline__ void gemm_core_h(const __half* __restrict__ A,
                                            const __half* __restrict__ W,
                                            int m0, int n0,
                                            float acc[2][8][4]){
    extern __shared__ __half smh[];
    const int tid = threadIdx.x;
    const int wid = tid >> 5, lane = tid & 31;
    const int mw0 = (wid >> 1) * 32;
    const int nw0 = (wid & 1) * 64;
    const uint32_t sb = smem_u32(smh);

    // ldmatrix lane geometry: tile t = lane>>3; row += (t&1)*8; k += (t>>1)*8
    const int rowoff = (lane & 7) + ((lane >> 3) & 1) * 8;
    const int koff   = (lane >> 4) * 8;

#pragma unroll
    for (int c = 0; c < NS-1; c++){
        uint32_t st = sb + c*STAGE_H*2;
        load_chunk_h(A, W, m0, n0, c*TKH, st, st + TILE_H*2, tid);
        cp_commit();
    }

    for (int c = 0; c < NCHUNK; c++){
        cp_wait2();            // chunk c resident (c+1, c+2 may be in flight)
        __syncthreads();
        if (c + 3 < NCHUNK){
            uint32_t st = sb + ((c+3)%NS)*STAGE_H*2;
            load_chunk_h(A, W, m0, n0, (c+3)*TKH, st, st + TILE_H*2, tid);
        }
        cp_commit();

        const uint32_t fa = sb + (c%NS)*STAGE_H*2;
        const uint32_t fw = fa + TILE_H*2;

#pragma unroll
        for (int ks = 0; ks < 2; ks++){
            const int kb = ks*16 + koff;
            uint32_t afr[2][4];
#pragma unroll
            for (int mi = 0; mi < 2; mi++)
                ldsm_x4(afr[mi], fa + ((mw0 + mi*16 + rowoff)*ROWH + kb)*2);
            uint32_t bfr[4][4];
#pragma unroll
            for (int p = 0; p < 4; p++)
                ldsm_x4(bfr[p], fw + ((nw0 + p*16 + rowoff)*ROWH + kb)*2);
#pragma unroll
            for (int p = 0; p < 4; p++){
                uint32_t b0[2] = {bfr[p][0], bfr[p][2]};   // ni = 2p
                uint32_t b1[2] = {bfr[p][1], bfr[p][3]};   // ni = 2p+1
#pragma unroll
                for (int mi = 0; mi < 2; mi++){
                    mma_f16_16x8x16(acc[mi][2*p],   afr[mi], b0);
                    mma_f16_16x8x16(acc[mi][2*p+1], afr[mi], b1);
                }
            }
        }
        __syncthreads();
    }
}

// fused q/k/v projection: blockIdx.x in [0,24): which = x>>3
__global__ __launch_bounds__(256,2)
void tc_gemm_qkv(const __half* __restrict__ A, const __half* __restrict__ Wh,
                 float* __restrict__ C0, float* __restrict__ C1,
                 float* __restrict__ C2)
{
    const int which = blockIdx.x >> 3;
    const int m0 = blockIdx.y * TM, n0 = (blockIdx.x & 7) * TN;
    const __half* W = Wh + (size_t)which * E_ * E_;
    float* C = (which == 0) ? C0 : (which == 1) ? C1 : C2;
    const bool act = (which < 2);

    float acc[2][8][4];
#pragma unroll
    for (int mi = 0; mi < 2; mi++)
#pragma unroll
        for (int ni = 0; ni < 8; ni++)
#pragma unroll
            for (int j = 0; j < 4; j++) acc[mi][ni][j] = 0.f;

    gemm_core_h(A, W, m0, n0, acc);

    const int wid = threadIdx.x >> 5, lane = threadIdx.x & 31;
    const int mw0 = (wid >> 1) * 32, nw0 = (wid & 1) * 64;
    const int r = lane >> 2, tig = lane & 3;
#pragma unroll
    for (int mi = 0; mi < 2; mi++){
#pragma unroll
        for (int ni = 0; ni < 8; ni++){
            const int row = m0 + mw0 + mi*16 + r;
            const int col = n0 + nw0 + ni*8 + tig*2;
            float v[4];
#pragma unroll
            for (int j = 0; j < 4; j++){
                float x = acc[mi][ni][j];
                if (act) x = (x > 0.f) ? (x + 1.f) : expf(x);
                v[j] = x;
            }
            float2 lo = {v[0], v[1]}, hi = {v[2], v[3]};
            *(float2*)&C[(size_t)row * E_ + col]     = lo;
            *(float2*)&C[(size_t)(row+8) * E_ + col] = hi;
        }
    }
}

// output projection with bias
__global__ __launch_bounds__(256,2)
void tc_gemm_out(const __half* __restrict__ A, const __half* __restrict__ Wh,
                 const float* __restrict__ bias, float* __restrict__ C)
{
    const int m0 = blockIdx.y * TM, n0 = blockIdx.x * TN;
    const __half* W = Wh + (size_t)3 * E_ * E_;

    float acc[2][8][4];
#pragma unroll
    for (int mi = 0; mi < 2; mi++)
#pragma unroll
        for (int ni = 0; ni < 8; ni++)
#pragma unroll
            for (int j = 0; j < 4; j++) acc[mi][ni][j] = 0.f;

    gemm_core_h(A, W, m0, n0, acc);

    const int wid = threadIdx.x >> 5, lane = threadIdx.x & 31;
    const int mw0 = (wid >> 1) * 32, nw0 = (wid & 1) * 64;
    const int r = lane >> 2, tig = lane & 3;
#pragma unroll
    for (int mi = 0; mi < 2; mi++){
#pragma unroll
        for (int ni = 0; ni < 8; ni++){
            const int row = m0 + mw0 + mi*16 + r;
            const int col = n0 + nw0 + ni*8 + tig*2;
            float b0 = bias[col], b1 = bias[col+1];
            float2 lo = {acc[mi][ni][0] + b0, acc[mi][ni][1] + b1};
            float2 hi = {acc[mi][ni][2] + b0, acc[mi][ni][3] + b1};
            *(float2*)&C[(size_t)row * E_ + col]     = lo;
            *(float2*)&C[(size_t)(row+8) * E_ + col] = hi;
        }
    }
}

// =================================================================
// kv/zk per chunk: kv[d,e] = sum_c phi_k[c,d]*v[c,e]; zk[d]=sum_c phi_k[c,d]
// =================================================================
__global__ __launch_bounds__(256)
void kv_kernel(const float* __restrict__ k, const float* __restrict__ v,
               float* __restrict__ kv, float* __restrict__ zk)
{
    extern __shared__ float sm[];
    float* sk = sm;              // 128*68
    float* sv = sm + 128*68;     // 128*68

    const int bid = blockIdx.x;
    const int n = bid % NC;
    const int h = (bid / NC) % H_;
    const int b = bid / (NC * H_);
    const int tid = threadIdx.x;

    const float* kb = k + (size_t)(b*T_ + n*CH) * E_ + h*D_;
    const float* vb = v + (size_t)(b*T_ + n*CH) * E_ + h*D_;

#pragma unroll
    for (int it = 0; it < 8; it++) {
        int idx4 = tid + it * 256;
        int c  = idx4 >> 4;
        int d0 = (idx4 & 15) << 2;
        *(float4*)&sk[c*68 + d0] = *(const float4*)&kb[(size_t)c * E_ + d0];
        *(float4*)&sv[c*68 + d0] = *(const float4*)&vb[(size_t)c * E_ + d0];
    }
    __syncthreads();

    const int tx = tid & 15, ty = tid >> 4;
    float acc[4][4];
#pragma unroll
    for (int i = 0; i < 4; i++)
#pragma unroll
        for (int j = 0; j < 4; j++) acc[i][j] = 0.f;

#pragma unroll 8
    for (int c = 0; c < 128; c++) {
        float4 kf = *(const float4*)&sk[c*68 + ty*4];
        float4 vf = *(const float4*)&sv[c*68 + tx*4];
        float ka[4] = {kf.x, kf.y, kf.z, kf.w};
        float va[4] = {vf.x, vf.y, vf.z, vf.w};
#pragma unroll
        for (int i = 0; i < 4; i++)
#pragma unroll
            for (int j = 0; j < 4; j++)
                acc[i][j] += ka[i] * va[j];
    }

    float* kvb = kv + (size_t)bid * (D_*D_);
#pragma unroll
    for (int i = 0; i < 4; i++) {
        float4 o = {acc[i][0], acc[i][1], acc[i][2], acc[i][3]};
        *(float4*)&kvb[(ty*4 + i) * D_ + tx*4] = o;
    }

    if (tid < D_) {
        float s = 0.f;
        for (int c = 0; c < 128; c++) s += sk[c*68 + tid];
        zk[(size_t)bid * D_ + tid] = s;
    }
}

// =================================================================
// exclusive prefix over chunks (N=16) per (b,h)
// =================================================================
__global__ __launch_bounds__(256)
void prefix_kernel(const float* __restrict__ kv, const float* __restrict__ zk,
                   float* __restrict__ S, float* __restrict__ Z)
{
    const int bh = blockIdx.x;
    const size_t base = (size_t)bh * NC * (D_*D_);
    for (int i = threadIdx.x; i < D_*D_; i += blockDim.x) {
        float run = 0.f;
        for (int n = 0; n < NC; n++) {
            S[base + (size_t)n * (D_*D_) + i] = run;
            run += kv[base + (size_t)n * (D_*D_) + i];
        }
    }
    const size_t zb = (size_t)bh * NC * D_;
    for (int i = threadIdx.x; i < D_; i += blockDim.x) {
        float run = 0.f;
        for (int n = 0; n < NC; n++) {
            Z[zb + (size_t)n * D_ + i] = run;
            run += zk[zb + (size_t)n * D_ + i];
        }
    }
}

// =================================================================
// intra-chunk attention (fp32 math; writes y as fp16 for final GEMM)
// =================================================================
#define ATTN_SMEM_FLOATS 38336
__global__ __launch_bounds__(256)
void attn_kernel(const float* __restrict__ q, const float* __restrict__ k,
                 const float* __restrict__ v, const float* __restrict__ S,
                 const float* __restrict__ Z, __half* __restrict__ y)
{
    extern __shared__ float sm[];
    float* sqT  = sm;
    float* skv  = sm + 8192;
    float* sAT  = sm + 16896;
    float* sS   = sm + 33792;
    float* sZ   = sm + 38144;
    float* sden = sm + 38208;

    const int bid = blockIdx.x;
    const int n = bid % NC;
    const int h = (bid / NC) % H_;
    const int b = bid / (NC * H_);
    const int tid = threadIdx.x, tx = tid & 15, ty = tid >> 4;

    const float* qb = q + (size_t)(b*T_ + n*CH) * E_ + h*D_;
    const float* kb = k + (size_t)(b*T_ + n*CH) * E_ + h*D_;
    const float* vb = v + (size_t)(b*T_ + n*CH) * E_ + h*D_;
    const float* Sb = S + (size_t)bid * (D_*D_);
    const float* Zb = Z + (size_t)bid * D_;

#pragma unroll
    for (int it = 0; it < 8; it++) {
        int idx4 = tid + it * 256;
        int c  = idx4 >> 4;
        int d0 = (idx4 & 15) << 2;
        float4 vq = *(const float4*)&qb[(size_t)c * E_ + d0];
        sqT[(d0+0)*128 + c] = vq.x;
        sqT[(d0+1)*128 + c] = vq.y;
        sqT[(d0+2)*128 + c] = vq.z;
        sqT[(d0+3)*128 + c] = vq.w;
        float4 vk = *(const float4*)&kb[(size_t)c * E_ + d0];
        skv[(d0+0)*128 + c] = vk.x;
        skv[(d0+1)*128 + c] = vk.y;
        skv[(d0+2)*128 + c] = vk.z;
        skv[(d0+3)*128 + c] = vk.w;
    }
    __syncthreads();

    float acc[8][8];
#pragma unroll
    for (int i = 0; i < 8; i++)
#pragma unroll
        for (int j = 0; j < 8; j++) acc[i][j] = 0.f;

#pragma unroll 8
    for (int kk = 0; kk < 64; kk++) {
        float af[8], bf[8];
        *(float4*)&af[0] = *(const float4*)&sqT[kk*128 + ty*8];
        *(float4*)&af[4] = *(const float4*)&sqT[kk*128 + ty*8 + 4];
        *(float4*)&bf[0] = *(const float4*)&skv[kk*128 + tx*8];
        *(float4*)&bf[4] = *(const float4*)&skv[kk*128 + tx*8 + 4];
#pragma unroll
        for (int i = 0; i < 8; i++)
#pragma unroll
            for (int j = 0; j < 8; j++)
                acc[i][j] += af[i] * bf[j];
    }

    const int c0 = ty*8, s0 = tx*8;
#pragma unroll
    for (int j = 0; j < 8; j++) {
        int s = s0 + j;
#pragma unroll
        for (int i = 0; i < 8; i++)
            if (s > c0 + i) acc[i][j] = 0.f;
        float4 t0 = {acc[0][j], acc[1][j], acc[2][j], acc[3][j]};
        *(float4*)&sAT[s*132 + c0] = t0;
        float4 t1 = {acc[4][j], acc[5][j], acc[6][j], acc[7][j]};
        *(float4*)&sAT[s*132 + c0 + 4] = t1;
    }
    __syncthreads();

#pragma unroll
    for (int it = 0; it < 8; it++) {
        int idx4 = tid + it * 256;
        int c  = idx4 >> 4;
        int e0 = (idx4 & 15) << 2;
        *(float4*)&skv[c*68 + e0] = *(const float4*)&vb[(size_t)c * E_ + e0];
    }
#pragma unroll
    for (int it = 0; it < 4; it++) {
        int idx4 = tid + it * 256;
        int d  = idx4 >> 4;
        int e0 = (idx4 & 15) << 2;
        *(float4*)&sS[d*68 + e0] = *(const float4*)&Sb[d*D_ + e0];
    }
    if (tid < 16)
        *(float4*)&sZ[tid*4] = *(const float4*)&Zb[tid*4];
    __syncthreads();

    if (tid < 128) {
        float s = EPS;
        for (int ss = 0; ss < 128; ss++) s += sAT[ss*132 + tid];
        for (int d = 0; d < 64; d++)     s += sqT[d*128 + tid] * sZ[d];
        sden[tid] = s;
    }
    __syncthreads();

    float num[8][4];
#pragma unroll
    for (int i = 0; i < 8; i++)
#pragma unroll
        for (int j = 0; j < 4; j++) num[i][j] = 0.f;

#pragma unroll 8
    for (int ss = 0; ss < 128; ss++) {
        float af[8];
        *(float4*)&af[0] = *(const float4*)&sAT[ss*132 + ty*8];
        *(float4*)&af[4] = *(const float4*)&sAT[ss*132 + ty*8 + 4];
        float4 vf = *(const float4*)&skv[ss*68 + tx*4];
        float vv[4] = {vf.x, vf.y, vf.z, vf.w};
#pragma unroll
        for (int i = 0; i < 8; i++)
#pragma unroll
            for (int j = 0; j < 4; j++)
                num[i][j] += af[i] * vv[j];
    }
#pragma unroll 8
    for (int d = 0; d < 64; d++) {
        float af[8];
        *(float4*)&af[0] = *(const float4*)&sqT[d*128 + ty*8];
        *(float4*)&af[4] = *(const float4*)&sqT[d*128 + ty*8 + 4];
        float4 sf = *(const float4*)&sS[d*68 + tx*4];
        float svv[4] = {sf.x, sf.y, sf.z, sf.w};
#pragma unroll
        for (int i = 0; i < 8; i++)
#pragma unroll
            for (int j = 0; j < 4; j++)
                num[i][j] += af[i] * svv[j];
    }

    __half* yb = y + (size_t)(b*T_ + n*CH) * E_ + h*D_;
#pragma unroll
    for (int i = 0; i < 8; i++) {
        int c = ty*8 + i;
        float inv = 1.f / sden[c];
        __half2 h0 = __floats2half2_rn(num[i][0]*inv, num[i][1]*inv);
        __half2 h1 = __floats2half2_rn(num[i][2]*inv, num[i][3]*inv);
        uint2 o = {*(uint32_t*)&h0, *(uint32_t*)&h1};
        *(uint2*)&yb[(size_t)c * E_ + tx*4] = o;
    }
}

// =================================================================
extern "C" void kernel_launch(void* const* d_in, const int* in_sizes, int n_in,
                              void* d_out, int out_size)
{
    const float* x  = (const float*)d_in[0];
    const float* Wq = (const float*)d_in[1];
    const float* Wk = (const float*)d_in[2];
    const float* Wv = (const float*)d_in[3];
    const float* Wp = (const float*)d_in[4];
    const float* bp = (const float*)d_in[5];
    float* out = (float*)d_out;

    float *q, *k, *v, *kv, *zk, *S, *Z;
    __half *xh, *yh, *wh;
    cudaGetSymbolAddress((void**)&q,  g_q);
    cudaGetSymbolAddress((void**)&k,  g_k);
    cudaGetSymbolAddress((void**)&v,  g_v);
    cudaGetSymbolAddress((void**)&xh, g_xh);
    cudaGetSymbolAddress((void**)&yh, g_yh);
    cudaGetSymbolAddress((void**)&wh, g_wh);
    cudaGetSymbolAddress((void**)&kv, g_kv);
    cudaGetSymbolAddress((void**)&zk, g_zk);
    cudaGetSymbolAddress((void**)&S,  g_S);
    cudaGetSymbolAddress((void**)&Z,  g_Z);

    const int kv_smem   = 2 * 128 * 68 * (int)sizeof(float);
    const int attn_smem = ATTN_SMEM_FLOATS * (int)sizeof(float);
    cudaFuncSetAttribute(kv_kernel,   cudaFuncAttributeMaxDynamicSharedMemorySize, kv_smem);
    cudaFuncSetAttribute(attn_kernel, cudaFuncAttributeMaxDynamicSharedMemorySize, attn_smem);
    cudaFuncSetAttribute(tc_gemm_qkv, cudaFuncAttributeMaxDynamicSharedMemorySize, GEMM_SMEM);
    cudaFuncSetAttribute(tc_gemm_out, cudaFuncAttributeMaxDynamicSharedMemorySize, GEMM_SMEM);

    dim3 blk(256);

    // one-time fp16 conversion of GEMM inputs
    f2h_kernel<<<(M_*E_)/2048, blk>>>(x,  xh, M_*E_);
    f2h_kernel<<<(E_*E_)/2048, blk>>>(Wq, wh + 0*(size_t)E_*E_, E_*E_);
    f2h_kernel<<<(E_*E_)/2048, blk>>>(Wk, wh + 1*(size_t)E_*E_, E_*E_);
    f2h_kernel<<<(E_*E_)/2048, blk>>>(Wv, wh + 2*(size_t)E_*E_, E_*E_);
    f2h_kernel<<<(E_*E_)/2048, blk>>>(Wp, wh + 3*(size_t)E_*E_, E_*E_);

    tc_gemm_qkv<<<dim3(24, M_/TM), blk, GEMM_SMEM>>>(xh, wh, q, k, v);

    kv_kernel<<<B_*H_*NC, blk, kv_smem>>>(k, v, kv, zk);
    prefix_kernel<<<B_*H_, blk>>>(kv, zk, S, Z);
    attn_kernel<<<B_*H_*NC, blk, attn_smem>>>(q, k, v, S, Z, yh);

    tc_gemm_out<<<dim3(8, M_/TM), blk, GEMM_SMEM>>>(yh, wh, bp, out);
}